// round 14
// baseline (speedup 1.0000x reference)
#include <cuda_runtime.h>
#include <cuda_bf16.h>

// x (64, 96, 8, 8) fp32 -> out (64, 96, 96, 8, 8, 2) fp32
// out[b,i,j,c1,c2,0] = x[b,i,c1,c2]; out[b,i,j,c1,c2,1] = x[b,j,c1,c2]
//
// SMEM-staged variant: keep the proven store structure (4 independent
// 512B-coalesced STG.128 per thread), but serve ALL operand reads from
// shared memory so the L1tex wavefront queue carries stores only.
//
// Block = (b, i, jt): 128 threads / 4 warps, 16 j's.
// Phase 1: cooperative LDG of 17 rows (16 xj + xi = 4352B) into SMEM.
// Phase 2: warp w stores j = jt*16 + w*4 + {0..3}; lane = k2 (0..31);
//          operands via LDS (separate smem crossbar, not L1tex queue).

#define GS  96
#define BLK 64            // 8*8 floats per group block
#define F4  32            // float4 per (b,i,j) pair
#define JT  6             // j-tiles per (b,i): 6 * 16 = 96

__global__ __launch_bounds__(128)
void gcom_kernel(const float* __restrict__ x, float4* __restrict__ out)
{
    __shared__ float s[17 * BLK];          // rows 0..15 = xj tile, row 16 = xi

    unsigned blk = blockIdx.x;             // (b*96 + i)*6 + jt
    unsigned jt  = blk % JT;
    unsigned bi  = blk / JT;               // b*96 + i
    unsigned b   = bi / GS;
    unsigned i   = bi - b * GS;
    unsigned j0  = jt * 16;                // block's first j

    unsigned tid = threadIdx.x;

    // Phase 1: fill SMEM. 17 rows * 16 float4 = 272 float4, 128 threads.
    const float* xb = x + (size_t)b * GS * BLK;
#pragma unroll
    for (unsigned t = 0; t < 3; ++t) {
        unsigned idx = tid + t * 128u;     // 0..271 (272..383 masked)
        if (idx < 272u) {
            unsigned r = idx >> 4;         // row 0..16
            unsigned q = idx & 15u;        // float4 within row
            unsigned src = (r < 16u) ? (j0 + r) : i;
            ((float4*)s)[idx] = __ldg((const float4*)(xb + src * BLK) + q);
        }
    }
    __syncthreads();

    // Phase 2: stores. lane = k2, warp w covers 4 consecutive j's.
    unsigned lane = tid & 31u;
    unsigned w    = tid >> 5;              // warp 0..3
    unsigned jw   = w * 4;                 // j offset within tile

    float2 a  = ((const float2*)(s + 16 * BLK))[lane];
    const float2* cj = (const float2*)(s + jw * BLK) + lane;
    float2 c0 = cj[0];
    float2 c1 = cj[F4];
    float2 c2 = cj[2 * F4];
    float2 c3 = cj[3 * F4];

    float4* o = out + ((size_t)bi * GS + j0 + jw) * F4 + lane;
    __stcs(o,          make_float4(a.x, c0.x, a.y, c0.y));
    __stcs(o + F4,     make_float4(a.x, c1.x, a.y, c1.y));
    __stcs(o + 2 * F4, make_float4(a.x, c2.x, a.y, c2.y));
    __stcs(o + 3 * F4, make_float4(a.x, c3.x, a.y, c3.y));
}

extern "C" void kernel_launch(void* const* d_in, const int* in_sizes, int n_in,
                              void* d_out, int out_size)
{
    const float* x = (const float*)d_in[0];
    float4* out = (float4*)d_out;

    // 64 * 96 * 6 = 36864 blocks; each writes 16 * 512B = 8KB of output.
    gcom_kernel<<<64 * GS * JT, 128>>>(x, out);
}